// round 5
// baseline (speedup 1.0000x reference)
#include <cuda_runtime.h>
#include <math.h>

#define T 1024
#define B 32
#define INPUT_DIM 256
#define H 512
#define H3 1536
#define FEAT (2*H)

#define NC_DIR 64             // CTAs per direction
#define NFLAGS 512            // producer warps per direction

// ---- device scratch ----
__device__ __align__(256) float g_xT[T * INPUT_DIM * B];              // tf32 bits
__device__ __align__(256) float g_Xi[2u * T * H3 * B];                // fp32
__device__ __align__(256) float g_yA[T * FEAT * B];                   // tf32 bits
__device__ __align__(256) float g_yB[T * FEAT * B];                   // tf32 bits
__device__ __align__(256) float g_htf[2][2][H][B];                    // tf32 bits
__device__ __align__(16) unsigned g_flag[2][NFLAGS];                  // per-warp step flags

// ---------------- helpers ----------------------------------------------------
__device__ __forceinline__ unsigned cvt_tf32(float f) {
    unsigned r;
    asm("cvt.rna.tf32.f32 %0, %1;" : "=r"(r) : "f"(f));
    return r;
}

__device__ __forceinline__ void mma8(float* d, const unsigned* a,
                                     unsigned b0, unsigned b1) {
    asm("mma.sync.aligned.m16n8k8.row.col.f32.tf32.tf32.f32 "
        "{%0,%1,%2,%3},{%4,%5,%6,%7},{%8,%9},{%0,%1,%2,%3};"
        : "+f"(d[0]), "+f"(d[1]), "+f"(d[2]), "+f"(d[3])
        : "r"(a[0]), "r"(a[1]), "r"(a[2]), "r"(a[3]), "r"(b0), "r"(b1));
}

// wait until ALL NFLAGS flags of this direction are >= tgt (warp-cooperative)
__device__ __forceinline__ void poll_all(const unsigned* fl, unsigned tgt) {
    int l = threadIdx.x & 31;
    const int4* p = (const int4*)fl + l * 4;     // 16 flags per lane
    for (;;) {
        int4 a = __ldcg(p);
        int4 b = __ldcg(p + 1);
        int4 c = __ldcg(p + 2);
        int4 d = __ldcg(p + 3);
        unsigned m = (unsigned)a.x;
        m = min(m, (unsigned)a.y); m = min(m, (unsigned)a.z); m = min(m, (unsigned)a.w);
        m = min(m, (unsigned)b.x); m = min(m, (unsigned)b.y); m = min(m, (unsigned)b.z); m = min(m, (unsigned)b.w);
        m = min(m, (unsigned)c.x); m = min(m, (unsigned)c.y); m = min(m, (unsigned)c.z); m = min(m, (unsigned)c.w);
        m = min(m, (unsigned)d.x); m = min(m, (unsigned)d.y); m = min(m, (unsigned)d.z); m = min(m, (unsigned)d.w);
        if (__all_sync(0xffffffffu, m >= tgt)) break;
        __nanosleep(64);
    }
    asm volatile("fence.acq_rel.gpu;" ::: "memory");
}

// ---------------- transpose + tf32 round: x[t][b][k] -> g_xT[t][k][b] --------
__global__ void transpose_x(const float* __restrict__ x) {
    __shared__ float sm[B][INPUT_DIM + 1];
    int t = blockIdx.x;
    const float* xin = x + (size_t)t * B * INPUT_DIM;
    for (int i = threadIdx.x; i < B * INPUT_DIM; i += 256) {
        int b = i >> 8, k = i & 255;
        sm[b][k] = xin[i];
    }
    __syncthreads();
    float* xo = g_xT + (size_t)t * INPUT_DIM * B;
    for (int i = threadIdx.x; i < B * INPUT_DIM; i += 256) {
        int k = i >> 5, b = i & 31;
        xo[i] = __uint_as_float(cvt_tf32(sm[b][k]));
    }
}

// ---------------- Xi GEMM (tf32 tensor cores) -------------------------------
__global__ __launch_bounds__(256) void gemm_xi(const float* __restrict__ A,
                                               const float* __restrict__ Wih,
                                               const float* __restrict__ bih,
                                               int K) {
    __shared__ float Ws[128 * 36];
    __shared__ float xs[4 * 32 * 40];

    // zero the recurrence flags for the following gru_rec launch (stream order)
    if (blockIdx.x == 0 && blockIdx.y == 0 && threadIdx.x < 256)
        ((int4*)g_flag)[threadIdx.x] = make_int4(0, 0, 0, 0);

    int t0  = blockIdx.x * 4;
    int dir = blockIdx.y / 12;
    int g0  = (blockIdx.y % 12) * 128;
    int tid = threadIdx.x;
    int l   = tid & 31;
    int w   = tid >> 5;
    int wm  = w & 3;
    int wn  = w >> 2;

    const float* Wp = Wih + ((size_t)dir * H3 + g0) * (size_t)K;

    float acc[2][8][4];
#pragma unroll
    for (int mt = 0; mt < 2; mt++)
#pragma unroll
        for (int q = 0; q < 8; q++)
#pragma unroll
            for (int s = 0; s < 4; s++) acc[mt][q][s] = 0.f;

    for (int k0 = 0; k0 < K; k0 += 32) {
#pragma unroll
        for (int i = 0; i < 4; i++) {
            int fid = tid + i * 256;
            int g = fid >> 3, kq = fid & 7;
            float4 wv = *(const float4*)&Wp[(size_t)g * K + k0 + kq * 4];
            float4 o;
            o.x = __uint_as_float(cvt_tf32(wv.x));
            o.y = __uint_as_float(cvt_tf32(wv.y));
            o.z = __uint_as_float(cvt_tf32(wv.z));
            o.w = __uint_as_float(cvt_tf32(wv.w));
            *(float4*)&Ws[g * 36 + kq * 4] = o;
        }
#pragma unroll
        for (int i = 0; i < 4; i++) {
            int fid = tid + i * 256;
            int tp = fid >> 8, k = (fid >> 3) & 31, bq = fid & 7;
            float4 xv = *(const float4*)&A[((size_t)(t0 + tp) * K + k0 + k) * B + bq * 4];
            *(float4*)&xs[tp * 1280 + k * 40 + bq * 4] = xv;
        }
        __syncthreads();

#pragma unroll
        for (int ki = 0; ki < 4; ki++) {
            unsigned a[2][4];
#pragma unroll
            for (int mt = 0; mt < 2; mt++) {
                int row = wm * 32 + mt * 16 + (l >> 2);
                int kk = ki * 8 + (l & 3);
                a[mt][0] = __float_as_uint(Ws[row * 36 + kk]);
                a[mt][1] = __float_as_uint(Ws[(row + 8) * 36 + kk]);
                a[mt][2] = __float_as_uint(Ws[row * 36 + kk + 4]);
                a[mt][3] = __float_as_uint(Ws[(row + 8) * 36 + kk + 4]);
            }
#pragma unroll
            for (int q = 0; q < 8; q++) {
                int n = wn * 64 + q * 8;
                int tp = n >> 5, bb = (n & 31) + (l >> 2);
                int kk = ki * 8 + (l & 3);
                unsigned b0 = __float_as_uint(xs[tp * 1280 + kk * 40 + bb]);
                unsigned b1 = __float_as_uint(xs[tp * 1280 + (kk + 4) * 40 + bb]);
                mma8(acc[0][q], a[0], b0, b1);
                mma8(acc[1][q], a[1], b0, b1);
            }
        }
        __syncthreads();
    }

    float bias[2][2];
#pragma unroll
    for (int mt = 0; mt < 2; mt++) {
        int r = g0 + wm * 32 + mt * 16 + (l >> 2);
        bias[mt][0] = bih[dir * H3 + r];
        bias[mt][1] = bih[dir * H3 + r + 8];
    }
#pragma unroll
    for (int mt = 0; mt < 2; mt++)
#pragma unroll
        for (int q = 0; q < 8; q++) {
            int n = wn * 64 + q * 8;
            int tp = n >> 5;
            int bb = (n & 31) + (l & 3) * 2;
            int r = g0 + wm * 32 + mt * 16 + (l >> 2);
            size_t base = (size_t)(dir * T + t0 + tp) * H3;
            float2 v0 = make_float2(acc[mt][q][0] + bias[mt][0],
                                    acc[mt][q][1] + bias[mt][0]);
            float2 v1 = make_float2(acc[mt][q][2] + bias[mt][1],
                                    acc[mt][q][3] + bias[mt][1]);
            *(float2*)&g_Xi[(base + r) * B + bb] = v0;
            *(float2*)&g_Xi[(base + r + 8) * B + bb] = v1;
        }
}

// ---------------- persistent recurrence (flag-sync) --------------------------
// 128 CTAs: dir = cta>>6, J0 = (cta&63)*8 -> 24 gate rows.
// Warp ws owns k-slice [ws*64,+64); W_hh A-frags in registers.
// Per-warp flags; double-buffered partials; one __syncthreads per step.
#define HST_W 2560                        // 64*40 floats per warp
#define HST_F (8 * HST_W)                 // 20480
#define PS_1  6144                        // 8 warps * 768
#define SMEM_REC ((HST_F + 2 * PS_1 + 64) * 4)

__global__ __launch_bounds__(256, 1) void gru_rec(const float* __restrict__ whh,
                                                  const float* __restrict__ bhh,
                                                  float* __restrict__ y,
                                                  float* __restrict__ out,
                                                  int layer) {
    extern __shared__ float smem[];
    float* Hst = smem;                    // warp-private staging
    float* Ps  = smem + HST_F;            // 2 parity buffers
    float* bias_s = smem + HST_F + 2 * PS_1;

    int cta = blockIdx.x;
    int dir = cta >> 6;
    int c64 = cta & 63;
    int J0  = c64 * 8;
    int tid = threadIdx.x;
    int l   = tid & 31;
    int ws  = tid >> 5;

    unsigned* flags = g_flag[dir];
    int myflag = c64 * 8 + ws;

    // preload W_hh A-fragments (2 m-tiles = 24 used rows) tf32
    unsigned afr[2][8][4];
    {
        const float* wp = whh + (size_t)dir * H3 * H;
#pragma unroll
        for (int mt = 0; mt < 2; mt++)
#pragma unroll
            for (int ki = 0; ki < 8; ki++)
#pragma unroll
                for (int s = 0; s < 4; s++) {
                    int r = mt * 16 + (l >> 2) + (s & 1) * 8;
                    int k = ws * 64 + ki * 8 + (l & 3) + (s >> 1) * 4;
                    float wv = 0.f;
                    if (r < 24)
                        wv = wp[(size_t)((r >> 3) * H + J0 + (r & 7)) * H + k];
                    afr[mt][ki][s] = cvt_tf32(wv);
                }
    }
    if (tid < 24)
        bias_s[tid] = bhh[dir * H3 + (tid >> 3) * H + J0 + (tid & 7)];

    // prologue: publish h0 = 0 for our row (warp ws owns row J0+ws)
    float hold = 0.f;
    g_htf[0][dir][J0 + ws][l] = 0.f;
    asm volatile("fence.acq_rel.gpu;" ::: "memory");
    if (l == 0) *((volatile unsigned*)&flags[myflag]) = 1u;

    float* HstW = Hst + ws * HST_W;
    const float4* hbase[2] = {(const float4*)&g_htf[0][dir][0][0],
                              (const float4*)&g_htf[1][dir][0][0]};

    // prefetch Xi for step 0 (row J0+ws, batch l)
    float xi0, xi1, xi2;
    {
        int t = dir ? (T - 1) : 0;
        const float* xip = g_Xi + (((size_t)dir * T + t) * H3 + J0 + ws) * B + l;
        xi0 = __ldg(xip);
        xi1 = __ldg(xip + (size_t)H * B);
        xi2 = __ldg(xip + (size_t)2 * H * B);
    }

    for (int step = 0; step < T; step++) {
        int t   = dir ? (T - 1 - step) : step;
        int cur = step & 1, nxt = cur ^ 1;
        int par = step & 1;

        // wait for h(step) from all producer warps of this direction
        poll_all(flags, (unsigned)(step + 1));

        // stage own k-slice [ws*64,+64) of h into warp-private smem
        const float4* hp = hbase[cur];
#pragma unroll
        for (int i = 0; i < 16; i++) {
            int idx = i * 32 + l;
            int kl = idx >> 3, b4 = idx & 7;
            float4 v = __ldcg(hp + (size_t)(ws * 64 + kl) * 8 + b4);
            *(float4*)&HstW[kl * 40 + b4 * 4] = v;
        }
        __syncwarp();

        // mma: 24(pad 32) x 32 x 64 per warp
        float acc[2][4][4];
#pragma unroll
        for (int mt = 0; mt < 2; mt++)
#pragma unroll
            for (int q = 0; q < 4; q++)
#pragma unroll
                for (int s = 0; s < 4; s++) acc[mt][q][s] = 0.f;

#pragma unroll
        for (int ki = 0; ki < 8; ki++) {
            int kk = ki * 8 + (l & 3);
#pragma unroll
            for (int q = 0; q < 4; q++) {
                int bb = q * 8 + (l >> 2);
                unsigned b0 = __float_as_uint(HstW[kk * 40 + bb]);
                unsigned b1 = __float_as_uint(HstW[(kk + 4) * 40 + bb]);
                mma8(acc[0][q], afr[0][ki], b0, b1);
                mma8(acc[1][q], afr[1][ki], b0, b1);
            }
        }

        // partials (rows 24..31 dropped) into parity buffer
        float* Pp = Ps + par * PS_1 + ws * 768;
#pragma unroll
        for (int q = 0; q < 4; q++) {
            int col = q * 8 + (l & 3) * 2;
            int r0 = (l >> 2);
            *(float2*)&Pp[r0 * 32 + col] = make_float2(acc[0][q][0], acc[0][q][1]);
            *(float2*)&Pp[(r0 + 8) * 32 + col] = make_float2(acc[0][q][2], acc[0][q][3]);
            *(float2*)&Pp[(r0 + 16) * 32 + col] = make_float2(acc[1][q][0], acc[1][q][1]);
        }
        __syncthreads();

        // epilogue: warp ws handles row J0+ws, lane l = batch
        {
            const float* Pr = Ps + par * PS_1;
            float s0 = 0.f, s1 = 0.f, s2 = 0.f;
#pragma unroll
            for (int wq = 0; wq < 8; wq++) {
                s0 += Pr[wq * 768 + ws * 32 + l];
                s1 += Pr[wq * 768 + (8 + ws) * 32 + l];
                s2 += Pr[wq * 768 + (16 + ws) * 32 + l];
            }
            float r = 1.f / (1.f + __expf(-(xi0 + s0 + bias_s[ws])));
            float z = 1.f / (1.f + __expf(-(xi1 + s1 + bias_s[8 + ws])));
            float n = tanhf(xi2 + r * (s2 + bias_s[16 + ws]));
            float hnew = (1.f - z) * n + z * hold;
            hold = hnew;

            float htf = __uint_as_float(cvt_tf32(hnew));
            g_htf[nxt][dir][J0 + ws][l] = htf;
            y[((size_t)t * FEAT + dir * H + (J0 + ws)) * B + l] = htf;
            if (step == T - 1)
                out[(2 * layer + dir) * (B * H) + l * H + (J0 + ws)] = hnew;
        }

        if (step + 1 < T) {
            // publish h(step+1)
            asm volatile("fence.acq_rel.gpu;" ::: "memory");
            if (l == 0) *((volatile unsigned*)&flags[myflag]) = (unsigned)(step + 2);

            // prefetch Xi for next step (hides under next poll)
            int tn = dir ? (T - 2 - step) : (step + 1);
            const float* xip = g_Xi + (((size_t)dir * T + tn) * H3 + J0 + ws) * B + l;
            xi0 = __ldg(xip);
            xi1 = __ldg(xip + (size_t)H * B);
            xi2 = __ldg(xip + (size_t)2 * H * B);
        }
    }
}

// ---------------- host launcher ---------------------------------------------
extern "C" void kernel_launch(void* const* d_in, const int* in_sizes, int n_in,
                              void* d_out, int out_size) {
    const float* x        = (const float*)d_in[0];
    const float* w_ih_l0  = (const float*)d_in[1];
    const float* w_hh_l0  = (const float*)d_in[2];
    const float* b_ih_l0  = (const float*)d_in[3];
    const float* b_hh_l0  = (const float*)d_in[4];
    const float* w_ih_lr  = (const float*)d_in[5];
    const float* w_hh_lr  = (const float*)d_in[6];
    const float* b_ih_lr  = (const float*)d_in[7];
    const float* b_hh_lr  = (const float*)d_in[8];
    float* out = (float*)d_out;

    cudaFuncSetAttribute(gru_rec, cudaFuncAttributeMaxDynamicSharedMemorySize,
                         SMEM_REC);

    void *pxT, *pyA, *pyB;
    cudaGetSymbolAddress(&pxT, g_xT);
    cudaGetSymbolAddress(&pyA, g_yA);
    cudaGetSymbolAddress(&pyB, g_yB);
    float* xT = (float*)pxT;
    float* yA = (float*)pyA;
    float* yB = (float*)pyB;

    dim3 ggrid(T / 4, 24);

    // layer 0
    transpose_x<<<T, 256>>>(x);
    gemm_xi<<<ggrid, 256>>>(xT, w_ih_l0, b_ih_l0, INPUT_DIM);
    gru_rec<<<2 * NC_DIR, 256, SMEM_REC>>>(w_hh_l0, b_hh_l0, yA, out, 0);

    // layer 1
    gemm_xi<<<ggrid, 256>>>(yA, w_ih_lr, b_ih_lr, FEAT);
    gru_rec<<<2 * NC_DIR, 256, SMEM_REC>>>(w_hh_lr, b_hh_lr, yB, out, 1);

    // layer 2
    gemm_xi<<<ggrid, 256>>>(yB, w_ih_lr + (size_t)2 * H3 * FEAT,
                            b_ih_lr + 2 * H3, FEAT);
    gru_rec<<<2 * NC_DIR, 256, SMEM_REC>>>(w_hh_lr + (size_t)2 * H3 * H,
                                           b_hh_lr + 2 * H3, yA, out, 2);
}